// round 16
// baseline (speedup 1.0000x reference)
#include <cuda_runtime.h>
#include <cuda_bf16.h>

// Problem constants
#define YY 5
#define NN 200000
#define GG 128
#define II 128
#define RR 3
#define BB 1024
#define KK 64
#define KTOT (RR * GG)   // 384

#define NWEFF_BLK 192    // weff-builder CTAs prepended to gather grid
#define MTOT (YY * BB)   // 5120

// Scratch (no cudaMalloc allowed)
// A (gathered means) split into bf16 hi/lo: A = hi + lo (+O(2^-17))
__device__ __align__(16) __nv_bfloat16 g_ahi[(size_t)MTOT * KTOT];
__device__ __align__(16) __nv_bfloat16 g_alo[(size_t)MTOT * KTOT];
// Weff TRANSPOSED [i][k] (mma .col operand), split hi/lo
__device__ __align__(16) __nv_bfloat16 g_wthi[II * KTOT];
__device__ __align__(16) __nv_bfloat16 g_wtlo[II * KTOT];

__device__ __forceinline__ void bf16_split(float x, __nv_bfloat16& hi, __nv_bfloat16& lo) {
    hi = __float2bfloat16(x);
    lo = __float2bfloat16(x - __bfloat162float(hi));
}

// ---------------------------------------------------------------------------
// Fused kernel #1 (1D grid, 128 threads) — EXACT R8 gather mainloop:
//   blocks [0, 192):         build Weff^T (hi/lo bf16)
//   blocks [192, 192+15360): gather + masked mean -> A (hi/lo bf16)
// ---------------------------------------------------------------------------
__global__ void __launch_bounds__(128) gather_mean_kernel(
        const float* __restrict__ emb,
        const void* __restrict__ nbr,
        const void* __restrict__ cnt,
        const float* __restrict__ Wrel,
        const float* __restrict__ Wcite) {
    const int bid = blockIdx.x;
    const int tid = threadIdx.x;

    if (bid < NWEFF_BLK) {
        #pragma unroll
        for (int j = 0; j < 2; ++j) {
            int idx = bid * 256 + j * 128 + tid;   // < 49152
            int k = idx / II;        // 0..383 (r*128+g)
            int i = idx - k * II;    // 0..127
            float v;
            if (k < GG)
                v = Wcite[idx] + Wcite[GG * II + idx] + Wcite[2 * GG * II + idx];
            else
                v = Wrel[idx];
            __nv_bfloat16 hi, lo;
            bf16_split(v, hi, lo);
            g_wthi[i * KTOT + k] = hi;   // transposed store
            g_wtlo[i * KTOT + k] = lo;
        }
        return;
    }

    const int gid = bid - NWEFF_BLK;
    const int y   = gid / (RR * BB);
    const int rem = gid - y * (RR * BB);
    const int r   = rem >> 10;
    const int b   = rem & (BB - 1);
    const int w    = tid >> 5;
    const int lane = tid & 31;

    __shared__ int   s_is64;
    __shared__ int   s_cnt;
    __shared__ __align__(16) int   sidx[KK];
    __shared__ __align__(16) float part[4][GG];

    // dtype detection (warp 0): odd words of first 32 int64 candidates
    if (w == 0) {
        unsigned int v = ((const unsigned int*)cnt)[2 * lane + 1];
        unsigned int m = __ballot_sync(0xffffffffu, v != 0u);
        if (lane == 0) s_is64 = (m == 0u) ? 1 : 0;
    }
    __syncthreads();
    const int is64 = s_is64;

    const long long lin = ((long long)y * RR + r) * BB + b;
    if (tid == 0) {
        s_cnt = is64 ? (int)((const long long*)cnt)[lin]
                     : ((const int*)cnt)[lin];
    }
    if (tid < KK) {
        sidx[tid] = is64 ? (int)((const long long*)nbr)[lin * KK + tid]
                         : ((const int*)nbr)[lin * KK + tid];
    }
    __syncthreads();
    const int count = s_cnt;

    // float4 view of this year's embedding slab; row stride = 32 float4s
    const float4* e = (const float4*)(emb + (size_t)y * NN * GG) + lane;

    float4 acc = make_float4(0.f, 0.f, 0.f, 0.f);
    int k = w;
    for (; k + 4 < count; k += 8) {
        float4 v0 = e[(size_t)sidx[k] * 32];
        float4 v1 = e[(size_t)sidx[k + 4] * 32];
        acc.x += v0.x + v1.x;
        acc.y += v0.y + v1.y;
        acc.z += v0.z + v1.z;
        acc.w += v0.w + v1.w;
    }
    if (k < count) {
        float4 v0 = e[(size_t)sidx[k] * 32];
        acc.x += v0.x; acc.y += v0.y; acc.z += v0.z; acc.w += v0.w;
    }

    *(float4*)&part[w][lane * 4] = acc;
    __syncthreads();

    const float inv = 1.0f / (float)(count > 0 ? count : 1);
    float s = (part[0][tid] + part[1][tid] + part[2][tid] + part[3][tid]) * inv;

    __nv_bfloat16 hi, lo;
    bf16_split(s, hi, lo);
    const size_t o = ((size_t)y * BB + b) * KTOT + r * GG + tid;
    g_ahi[o] = hi;
    g_alo[o] = lo;
}

// ---------------------------------------------------------------------------
// Tensor-core GEMM: out[5120,128] = A[5120,384] @ Weff[384,128]
// 3-pass bf16 (hi*hi + hi*lo + lo*hi, fp32 accumulate) ~ fp32 precision.
// mma.sync.m16n8k16. Tile BM=32 x BN=64, 128 threads (4 warps), grid=320.
// Warp w: m-sub (w&1)*16, n-sub (w>>1)*32 -> warp tile 16x32 (4 n-tiles).
// Direct global fragment loads (A/W small and L1/L2-hot). Direct STG out.
// ---------------------------------------------------------------------------
#define GBM 32
#define GBN 64

__device__ __forceinline__ void mma_bf16(float* c, const unsigned* a,
                                         unsigned b0, unsigned b1) {
    asm volatile(
        "mma.sync.aligned.m16n8k16.row.col.f32.bf16.bf16.f32 "
        "{%0,%1,%2,%3}, {%4,%5,%6,%7}, {%8,%9}, {%0,%1,%2,%3};"
        : "+f"(c[0]), "+f"(c[1]), "+f"(c[2]), "+f"(c[3])
        : "r"(a[0]), "r"(a[1]), "r"(a[2]), "r"(a[3]), "r"(b0), "r"(b1));
}

__global__ void __launch_bounds__(128) gemm_mma_kernel(float* __restrict__ out) {
    const int tid  = threadIdx.x;
    const int w    = tid >> 5;
    const int lane = tid & 31;
    const int tq   = lane & 3;          // T%4
    const int tg   = lane >> 2;         // T/4

    const int mbase = (blockIdx.x >> 1) * GBM + (w & 1) * 16;
    const int nbase = (blockIdx.x & 1) * GBN + (w >> 1) * 32;

    const int arow0 = mbase + tg;       // A fragment rows arow0, arow0+8
    const int kcol  = tq * 2;           // A/B fragment k offset

    float acc[4][4];                    // [n-tile][c-frag]
    #pragma unroll
    for (int nt = 0; nt < 4; ++nt)
        #pragma unroll
        for (int i = 0; i < 4; ++i) acc[nt][i] = 0.f;

    const __nv_bfloat16* Ah0 = g_ahi + (size_t)arow0 * KTOT + kcol;
    const __nv_bfloat16* Ah1 = g_ahi + (size_t)(arow0 + 8) * KTOT + kcol;
    const __nv_bfloat16* Al0 = g_alo + (size_t)arow0 * KTOT + kcol;
    const __nv_bfloat16* Al1 = g_alo + (size_t)(arow0 + 8) * KTOT + kcol;
    const __nv_bfloat16* Wh  = g_wthi + (size_t)(nbase + tg) * KTOT + kcol;
    const __nv_bfloat16* Wl  = g_wtlo + (size_t)(nbase + tg) * KTOT + kcol;

    #pragma unroll 2
    for (int ks = 0; ks < KTOT / 16; ++ks) {
        const int kb = ks * 16;
        unsigned ah[4], al[4];
        ah[0] = *(const unsigned*)(Ah0 + kb);
        ah[1] = *(const unsigned*)(Ah1 + kb);
        ah[2] = *(const unsigned*)(Ah0 + kb + 8);
        ah[3] = *(const unsigned*)(Ah1 + kb + 8);
        al[0] = *(const unsigned*)(Al0 + kb);
        al[1] = *(const unsigned*)(Al1 + kb);
        al[2] = *(const unsigned*)(Al0 + kb + 8);
        al[3] = *(const unsigned*)(Al1 + kb + 8);

        #pragma unroll
        for (int nt = 0; nt < 4; ++nt) {
            const size_t bo = (size_t)(nt * 8) * KTOT + kb;
            unsigned bh0 = *(const unsigned*)(Wh + bo);
            unsigned bh1 = *(const unsigned*)(Wh + bo + 8);
            unsigned bl0 = *(const unsigned*)(Wl + bo);
            unsigned bl1 = *(const unsigned*)(Wl + bo + 8);
            mma_bf16(acc[nt], ah, bh0, bh1);   // hi*hi
            mma_bf16(acc[nt], ah, bl0, bl1);   // hi*lo
            mma_bf16(acc[nt], al, bh0, bh1);   // lo*hi
        }
    }

    // epilogue: c0,c1 -> (row, col..col+1); c2,c3 -> (row+8, ...)
    #pragma unroll
    for (int nt = 0; nt < 4; ++nt) {
        const int col = nbase + nt * 8 + tq * 2;
        float* o0 = out + (size_t)arow0 * II + col;
        float* o1 = out + (size_t)(arow0 + 8) * II + col;
        *(float2*)o0 = make_float2(acc[nt][0], acc[nt][1]);
        *(float2*)o1 = make_float2(acc[nt][2], acc[nt][3]);
    }
}

// ---------------------------------------------------------------------------
// kernel_launch: [weff-build + gather] -> tensor-core GEMM
// ---------------------------------------------------------------------------
extern "C" void kernel_launch(void* const* d_in, const int* in_sizes, int n_in,
                              void* d_out, int out_size) {
    const float* emb   = (const float*)d_in[0];
    const float* Wrel  = (const float*)d_in[1];
    const float* Wcite = (const float*)d_in[2];
    const void*  nbr   = d_in[3];
    const void*  cnt   = d_in[4];
    float* out = (float*)d_out;

    gather_mean_kernel<<<NWEFF_BLK + YY * RR * BB, 128>>>(emb, nbr, cnt, Wrel, Wcite);

    gemm_mma_kernel<<<(MTOT / GBM) * (II / GBN), 128>>>(out);
}

// round 17
// speedup vs baseline: 1.1158x; 1.1158x over previous
#include <cuda_runtime.h>
#include <cuda_bf16.h>

// Problem constants
#define YY 5
#define NN 200000
#define GG 128
#define II 128
#define RR 3
#define BB 1024
#define KK 64
#define KTOT (RR * GG)   // 384
#define KT16 (KTOT / 16) // 24 k16-tiles

#define NWEFF_BLK 192    // weff-builder CTAs prepended to gather grid
#define MTOT (YY * BB)   // 5120

// Scratch (no cudaMalloc allowed) — FRAGMENT-LAYOUT storage:
// A: tiles of (m16 x k16); tile t = 32 lanes x 16B (a0 a1 a2 a3 as bf16x2).
//    bf16 idx = tile*256 + lane*8 + reg*2 + kbit
// W^T: tiles of (n8 x k16); tile t = 32 lanes x 8B (b0 b1 as bf16x2).
//    bf16 idx = tile*128 + lane*4 + khalf*2 + kbit
__device__ __align__(16) __nv_bfloat16 g_ahi[(size_t)(MTOT / 16) * KT16 * 256];
__device__ __align__(16) __nv_bfloat16 g_alo[(size_t)(MTOT / 16) * KT16 * 256];
__device__ __align__(16) __nv_bfloat16 g_wthi[(II / 8) * KT16 * 128];
__device__ __align__(16) __nv_bfloat16 g_wtlo[(II / 8) * KT16 * 128];

__device__ __forceinline__ void bf16_split(float x, __nv_bfloat16& hi, __nv_bfloat16& lo) {
    hi = __float2bfloat16(x);
    lo = __float2bfloat16(x - __bfloat162float(hi));
}

// ---------------------------------------------------------------------------
// Fused kernel #1 (1D grid, 128 threads) — EXACT R8 gather mainloop:
//   blocks [0, 192):         build Weff^T in B-fragment layout (hi/lo)
//   blocks [192, 192+15360): gather + masked mean -> A in fragment layout
// ---------------------------------------------------------------------------
__global__ void __launch_bounds__(128) gather_mean_kernel(
        const float* __restrict__ emb,
        const void* __restrict__ nbr,
        const void* __restrict__ cnt,
        const float* __restrict__ Wrel,
        const float* __restrict__ Wcite) {
    const int bid = blockIdx.x;
    const int tid = threadIdx.x;

    if (bid < NWEFF_BLK) {
        #pragma unroll
        for (int j = 0; j < 2; ++j) {
            int idx = bid * 256 + j * 128 + tid;   // < 49152
            int k = idx / II;        // 0..383
            int i = idx - k * II;    // 0..127
            float v;
            if (k < GG)
                v = Wcite[idx] + Wcite[GG * II + idx] + Wcite[2 * GG * II + idx];
            else
                v = Wrel[idx];
            __nv_bfloat16 hi, lo;
            bf16_split(v, hi, lo);
            // B-fragment layout: b0 = W^T[n=tg][k=tq*2+{0,1}], b1 = k+8
            const int kin  = k & 15;
            const size_t tIdx = (size_t)(i >> 3) * KT16 + (k >> 4);
            const int lane2 = (i & 7) * 4 + ((kin >> 1) & 3);
            const size_t o = tIdx * 128 + lane2 * 4 + ((kin >> 3) << 1) + (kin & 1);
            g_wthi[o] = hi;
            g_wtlo[o] = lo;
        }
        return;
    }

    const int gid = bid - NWEFF_BLK;
    const int y   = gid / (RR * BB);
    const int rem = gid - y * (RR * BB);
    const int r   = rem >> 10;
    const int b   = rem & (BB - 1);
    const int w    = tid >> 5;
    const int lane = tid & 31;

    __shared__ int   s_is64;
    __shared__ int   s_cnt;
    __shared__ __align__(16) int   sidx[KK];
    __shared__ __align__(16) float part[4][GG];

    // dtype detection (warp 0): odd words of first 32 int64 candidates
    if (w == 0) {
        unsigned int v = ((const unsigned int*)cnt)[2 * lane + 1];
        unsigned int m = __ballot_sync(0xffffffffu, v != 0u);
        if (lane == 0) s_is64 = (m == 0u) ? 1 : 0;
    }
    __syncthreads();
    const int is64 = s_is64;

    const long long lin = ((long long)y * RR + r) * BB + b;
    if (tid == 0) {
        s_cnt = is64 ? (int)((const long long*)cnt)[lin]
                     : ((const int*)cnt)[lin];
    }
    if (tid < KK) {
        sidx[tid] = is64 ? (int)((const long long*)nbr)[lin * KK + tid]
                         : ((const int*)nbr)[lin * KK + tid];
    }
    __syncthreads();
    const int count = s_cnt;

    // float4 view of this year's embedding slab; row stride = 32 float4s
    const float4* e = (const float4*)(emb + (size_t)y * NN * GG) + lane;

    float4 acc = make_float4(0.f, 0.f, 0.f, 0.f);
    int k = w;
    for (; k + 4 < count; k += 8) {
        float4 v0 = e[(size_t)sidx[k] * 32];
        float4 v1 = e[(size_t)sidx[k + 4] * 32];
        acc.x += v0.x + v1.x;
        acc.y += v0.y + v1.y;
        acc.z += v0.z + v1.z;
        acc.w += v0.w + v1.w;
    }
    if (k < count) {
        float4 v0 = e[(size_t)sidx[k] * 32];
        acc.x += v0.x; acc.y += v0.y; acc.z += v0.z; acc.w += v0.w;
    }

    *(float4*)&part[w][lane * 4] = acc;
    __syncthreads();

    const float inv = 1.0f / (float)(count > 0 ? count : 1);
    float s = (part[0][tid] + part[1][tid] + part[2][tid] + part[3][tid]) * inv;

    __nv_bfloat16 hi, lo;
    bf16_split(s, hi, lo);
    // A-fragment layout store
    const int m    = y * BB + b;
    const int kin  = tid & 15;
    const size_t tIdx = (size_t)(m >> 4) * KT16 + (r * 8 + (tid >> 4));
    const int lane2 = (m & 7) * 4 + ((kin >> 1) & 3);
    const int reg   = ((m >> 3) & 1) + ((kin >> 3) << 1);
    const size_t o  = tIdx * 256 + lane2 * 8 + reg * 2 + (kin & 1);
    g_ahi[o] = hi;
    g_alo[o] = lo;
}

// ---------------------------------------------------------------------------
// Tensor-core GEMM: out[5120,128] = A[5120,384] @ Weff[384,128]
// 3-pass bf16 (hi*hi + hi*lo + lo*hi, fp32 accumulate).
// Fragment-layout operands: A fragment = ONE coalesced LDG.128 per warp,
// B fragment = ONE LDG.64 per warp. No smem, no ldmatrix, no shuffles.
// Tile 32x64: warp (w&1)=m-tile, (w>>1)=n-half (4 n8-tiles). grid = 320.
// ---------------------------------------------------------------------------
__device__ __forceinline__ void mma_bf16(float* c, const unsigned* a,
                                         unsigned b0, unsigned b1) {
    asm volatile(
        "mma.sync.aligned.m16n8k16.row.col.f32.bf16.bf16.f32 "
        "{%0,%1,%2,%3}, {%4,%5,%6,%7}, {%8,%9}, {%0,%1,%2,%3};"
        : "+f"(c[0]), "+f"(c[1]), "+f"(c[2]), "+f"(c[3])
        : "r"(a[0]), "r"(a[1]), "r"(a[2]), "r"(a[3]), "r"(b0), "r"(b1));
}

__global__ void __launch_bounds__(128) gemm_mma_kernel(float* __restrict__ out) {
    const int tid  = threadIdx.x;
    const int w    = tid >> 5;
    const int lane = tid & 31;
    const int tq   = lane & 3;
    const int tg   = lane >> 2;

    const int mtile = (blockIdx.x >> 1) * 2 + (w & 1);          // 0..319
    const int ntb   = (blockIdx.x & 1) * 8 + (w >> 1) * 4;      // n8-tile base

    float acc[4][4];
    #pragma unroll
    for (int nt = 0; nt < 4; ++nt)
        #pragma unroll
        for (int i = 0; i < 4; ++i) acc[nt][i] = 0.f;

    const uint4* Ah4 = (const uint4*)g_ahi;
    const uint4* Al4 = (const uint4*)g_alo;
    const uint2* Bh2 = (const uint2*)g_wthi;
    const uint2* Bl2 = (const uint2*)g_wtlo;

    #pragma unroll 4
    for (int ks = 0; ks < KT16; ++ks) {
        const size_t ai = (size_t)(mtile * KT16 + ks) * 32 + lane;
        uint4 ahv = Ah4[ai];
        uint4 alv = Al4[ai];
        unsigned ah[4] = {ahv.x, ahv.y, ahv.z, ahv.w};
        unsigned al[4] = {alv.x, alv.y, alv.z, alv.w};

        #pragma unroll
        for (int nt = 0; nt < 4; ++nt) {
            const size_t bi = (size_t)((ntb + nt) * KT16 + ks) * 32 + lane;
            uint2 bh = Bh2[bi];
            uint2 bl = Bl2[bi];
            mma_bf16(acc[nt], ah, bh.x, bh.y);   // hi*hi
            mma_bf16(acc[nt], ah, bl.x, bl.y);   // hi*lo
            mma_bf16(acc[nt], al, bh.x, bh.y);   // lo*hi
        }
    }

    const int row0 = mtile * 16 + tg;
    #pragma unroll
    for (int nt = 0; nt < 4; ++nt) {
        const int col = (ntb + nt) * 8 + tq * 2;
        *(float2*)(out + (size_t)row0 * II + col)       = make_float2(acc[nt][0], acc[nt][1]);
        *(float2*)(out + (size_t)(row0 + 8) * II + col) = make_float2(acc[nt][2], acc[nt][3]);
    }
}

// ---------------------------------------------------------------------------
// kernel_launch: [weff-build + gather] -> fragment-layout tensor GEMM
// ---------------------------------------------------------------------------
extern "C" void kernel_launch(void* const* d_in, const int* in_sizes, int n_in,
                              void* d_out, int out_size) {
    const float* emb   = (const float*)d_in[0];
    const float* Wrel  = (const float*)d_in[1];
    const float* Wcite = (const float*)d_in[2];
    const void*  nbr   = d_in[3];
    const void*  cnt   = d_in[4];
    float* out = (float*)d_out;

    gather_mean_kernel<<<NWEFF_BLK + YY * RR * BB, 128>>>(emb, nbr, cnt, Wrel, Wcite);

    gemm_mma_kernel<<<(MTOT / 32) * 2, 128>>>(out);
}